// round 12
// baseline (speedup 1.0000x reference)
#include <cuda_runtime.h>
#include <cuda_fp16.h>
#include <math.h>
#include <stdint.h>

#define NTOK    8192
#define DIM     1024
#define HID     2048
#define NEXP    8

// ---------------- scratch (device globals; no allocation allowed) ----------
__device__ __half g_x16[(size_t)NTOK * DIM];          // x_norm fp16
__device__ __half g_uw[(size_t)NEXP * 4096 * 1024];   // up W^T fp16, n' interleaved (a,g)
__device__ __half g_dw[(size_t)NEXP * 1024 * 2048];   // down W^T fp16 [e][n][k]
__device__ __half g_u [(size_t)NTOK * HID];           // swiglu out fp16
__device__ int g_tokmap[NEXP * NTOK];
__device__ int g_count[NEXP];

// ---------------- helpers ----------------------------------------------
__device__ __forceinline__ uint32_t smem_u32(const void* p) {
    uint32_t a;
    asm("{ .reg .u64 t; cvta.to.shared.u64 t, %1; cvt.u32.u64 %0, t; }" : "=r"(a) : "l"(p));
    return a;
}
__device__ __forceinline__ void cp16(uint32_t dst, const void* src) {
    asm volatile("cp.async.cg.shared.global [%0], [%1], 16;" :: "r"(dst), "l"(src));
}
#define CP_COMMIT() asm volatile("cp.async.commit_group;")
#define SWZ128(o) ((o) ^ (((o) >> 3) & 0x70))

__device__ __forceinline__ uint32_t pack_h(float a, float b) {
    __half2 h = __floats2half2_rn(a, b);
    return *(uint32_t*)&h;
}
__device__ __forceinline__ void ldsm4(uint32_t* r, uint32_t addr) {
    asm volatile("ldmatrix.sync.aligned.m8n8.x4.shared.b16 {%0,%1,%2,%3}, [%4];"
        : "=r"(r[0]), "=r"(r[1]), "=r"(r[2]), "=r"(r[3]) : "r"(addr));
}
__device__ __forceinline__ void mma16816(float* c, const uint32_t* a, uint32_t b0, uint32_t b1) {
    asm volatile("mma.sync.aligned.m16n8k16.row.col.f32.f16.f16.f32 "
        "{%0,%1,%2,%3}, {%4,%5,%6,%7}, {%8,%9}, {%0,%1,%2,%3};"
        : "+f"(c[0]), "+f"(c[1]), "+f"(c[2]), "+f"(c[3])
        : "r"(a[0]), "r"(a[1]), "r"(a[2]), "r"(a[3]), "r"(b0), "r"(b1));
}

// ---------------- smem layout (BM=128, BN=128, BK=64 fp16, 2-stage) --------
#define OFF_A    0
#define OFF_B    16384
#define STAGE_SZ 32768
#define SM_TILES 1024
#define SMEM_MMA 68608     // max(1024+2*32768, 1024+128*132*4) -> 3 CTAs/SM

// ====================================================================
__global__ void zero_counts_kernel() {
    if (threadIdx.x < NEXP) g_count[threadIdx.x] = 0;
}

// ====================================================================
// Kernel 1: RMSNorm + routing; writes x_norm fp16
// ====================================================================
__global__ __launch_bounds__(256)
void route_kernel(const float* __restrict__ x,
                  const float* __restrict__ scale,
                  const float* __restrict__ cent) {
    const int t = blockIdx.x, tid = threadIdx.x;
    const int lane = tid & 31, wid = tid >> 5;

    const float4 xv = ((const float4*)(x + (size_t)t * DIM))[tid];
    float ss = xv.x*xv.x + xv.y*xv.y + xv.z*xv.z + xv.w*xv.w;
    #pragma unroll
    for (int o = 16; o; o >>= 1) ss += __shfl_xor_sync(0xFFFFFFFFu, ss, o);
    __shared__ float swarp[8];
    if (lane == 0) swarp[wid] = ss;
    __syncthreads();
    float mean = 0.f;
    #pragma unroll
    for (int w = 0; w < 8; w++) mean += swarp[w];
    const float inv = rsqrtf(mean * (1.0f / DIM) + 1e-6f);

    const float4 sc = ((const float4*)scale)[tid];
    float v[4];
    v[0] = xv.x * (sc.x * inv); v[1] = xv.y * (sc.y * inv);
    v[2] = xv.z * (sc.z * inv); v[3] = xv.w * (sc.w * inv);

    ((uint2*)(g_x16 + (size_t)t * DIM))[tid] =
        make_uint2(pack_h(v[0], v[1]), pack_h(v[2], v[3]));

    float p[NEXP];
    #pragma unroll
    for (int e = 0; e < NEXP; e++) {
        const float4 c = ((const float4*)(cent + (size_t)e * DIM))[tid];
        p[e] = (c.x*c.x - 2.f*v[0]*c.x) + (c.y*c.y - 2.f*v[1]*c.y)
             + (c.z*c.z - 2.f*v[2]*c.z) + (c.w*c.w - 2.f*v[3]*c.w);
    }
    __shared__ float sred[NEXP][8];
    #pragma unroll
    for (int e = 0; e < NEXP; e++) {
        float s = p[e];
        #pragma unroll
        for (int o = 16; o; o >>= 1) s += __shfl_xor_sync(0xFFFFFFFFu, s, o);
        if (lane == 0) sred[e][wid] = s;
    }
    __syncthreads();
    if (tid == 0) {
        int best = 0; float bd = 3.4e38f;
        #pragma unroll
        for (int e = 0; e < NEXP; e++) {
            float d = 0.f;
            #pragma unroll
            for (int w = 0; w < 8; w++) d += sred[e][w];
            if (d < bd) { bd = d; best = e; }
        }
        int pos = atomicAdd(&g_count[best], 1);
        g_tokmap[best * NTOK + pos] = t;
    }
}

// ====================================================================
// Kernel 2a/2b: weight convert+transpose -> fp16, uint4 stores
// ====================================================================
__global__ __launch_bounds__(256)
void conv_up_kernel(const float* __restrict__ w) {   // [8][1024][4096]
    __shared__ float tile[32][65];
    const int e = blockIdx.z, n0 = blockIdx.x * 32, k0 = blockIdx.y * 64;
    const int tid = threadIdx.x;
    const float* W = w + ((size_t)e * 1024 + k0) * 4096 + n0;
    #pragma unroll
    for (int i = 0; i < 8; i++) {
        int idx = tid + i * 256;
        int kk = idx >> 5, nn = idx & 31;
        tile[nn][kk] = W[(size_t)kk * 4096 + nn];
    }
    __syncthreads();
    const int nn = tid >> 3, kq = tid & 7;
    const float* row = &tile[nn][kq * 8];
    uint4 v;
    v.x = pack_h(row[0], row[1]); v.y = pack_h(row[2], row[3]);
    v.z = pack_h(row[4], row[5]); v.w = pack_h(row[6], row[7]);
    int col = n0 + nn;
    int nprime = (col < 2048) ? (2 * col) : (2 * (col - 2048) + 1);
    *(uint4*)(g_uw + ((size_t)e * 4096 + nprime) * 1024 + k0 + kq * 8) = v;
}

__global__ __launch_bounds__(256)
void conv_down_kernel(const float* __restrict__ w) { // [8][2048][1024] -> [e][n][k]
    __shared__ float tile[32][65];
    const int e = blockIdx.z, n0 = blockIdx.x * 32, k0 = blockIdx.y * 64;
    const int tid = threadIdx.x;
    const float* W = w + ((size_t)e * 2048 + k0) * 1024 + n0;
    #pragma unroll
    for (int i = 0; i < 8; i++) {
        int idx = tid + i * 256;
        int kk = idx >> 5, nn = idx & 31;
        tile[nn][kk] = W[(size_t)kk * 1024 + nn];
    }
    __syncthreads();
    const int nn = tid >> 3, kq = tid & 7;
    const float* row = &tile[nn][kq * 8];
    uint4 v;
    v.x = pack_h(row[0], row[1]); v.y = pack_h(row[2], row[3]);
    v.z = pack_h(row[4], row[5]); v.w = pack_h(row[6], row[7]);
    *(uint4*)(g_dw + ((size_t)e * 1024 + n0 + nn) * 2048 + k0 + kq * 8) = v;
}

// ====================================================================
// Mainloop: BM=128, BN=128, BK=64 fp16, 256 thr, 8 warps (4m x 2n),
// warp tile 32m x 64n. 2-stage cp.async pipeline, 3 CTAs/SM.
// ====================================================================
__device__ __forceinline__ void load_chunk(uint32_t st, const int* rows_s, int tid,
                                           const __half* A, const __half* B,
                                           int n0, int k0, int kstride) {
    #pragma unroll
    for (int i = 0; i < 4; i++) {
        int idx = tid + i * 256;
        int r = idx >> 3, sg = idx & 7;
        uint32_t off = SWZ128((uint32_t)(r * 128 + sg * 16));
        cp16(st + OFF_A + off, A + (size_t)rows_s[r] * kstride + k0 + sg * 8);
        cp16(st + OFF_B + off, B + (size_t)(n0 + r) * kstride + k0 + sg * 8);
    }
}

__device__ __forceinline__ void compute_chunk(uint32_t st, int lane, int mbase, int nbase,
                                              float acc[2][8][4]) {
    const int rsel = lane & 15;
    const int csel = lane >> 4;
    #pragma unroll
    for (int k16 = 0; k16 < 4; k16++) {
        const int cg = k16 * 2 + csel;
        uint32_t a[2][4];
        #pragma unroll
        for (int mf = 0; mf < 2; mf++) {
            uint32_t boff = SWZ128((uint32_t)((mbase + mf*16 + rsel) * 128 + cg * 16));
            ldsm4(a[mf], st + OFF_A + boff);
        }
        #pragma unroll
        for (int q = 0; q < 4; q++) {
            uint32_t b[4];
            uint32_t boff = SWZ128((uint32_t)((nbase + q*16 + rsel) * 128 + cg * 16));
            ldsm4(b, st + OFF_B + boff);
            #pragma unroll
            for (int s = 0; s < 2; s++) {
                #pragma unroll
                for (int mf = 0; mf < 2; mf++)
                    mma16816(acc[mf][2*q + s], a[mf], b[s], b[2 + s]);
            }
        }
    }
}

// ====================================================================
// Kernel 3: up GEMM (fp16) + in-register SwiGLU (even n'=a, odd n'=g)
// ====================================================================
__global__ __launch_bounds__(256, 3)
void up_mma_kernel() {
    extern __shared__ char smem[];
    int* rows_s = (int*)smem;
    const uint32_t sb = smem_u32(smem);
    const int tid = threadIdx.x, lane = tid & 31, wid = tid >> 5;
    const int e = blockIdx.z;
    const int cnt = g_count[e];
    const int m0 = blockIdx.x * 128;
    if (m0 >= cnt) return;
    const int n0 = blockIdx.y * 128;     // n' base

    if (tid < 128) {
        int i = m0 + tid;
        rows_s[tid] = g_tokmap[e * NTOK + (i < cnt ? i : cnt - 1)];
    }
    __syncthreads();

    const __half* B = g_uw + (size_t)e * 4096 * 1024;

    const int NC = 16;   // 1024 / 64
    load_chunk(sb + SM_TILES, rows_s, tid, g_x16, B, n0, 0, DIM); CP_COMMIT();

    float acc[2][8][4];
    #pragma unroll
    for (int a = 0; a < 2; a++)
        #pragma unroll
        for (int b = 0; b < 8; b++)
            #pragma unroll
            for (int c = 0; c < 4; c++) acc[a][b][c] = 0.f;

    const int mbase = (wid & 3) * 32, nbase = (wid >> 2) * 64;

    #pragma unroll 1
    for (int c = 0; c < NC; c++) {
        asm volatile("cp.async.wait_group 0;" ::: "memory");
        __syncthreads();
        if (c + 1 < NC) {
            load_chunk(sb + SM_TILES + ((c+1)&1)*STAGE_SZ, rows_s, tid,
                       g_x16, B, n0, (c+1)*64, DIM);
            CP_COMMIT();
        }
        compute_chunk(sb + SM_TILES + (c&1)*STAGE_SZ, lane, mbase, nbase, acc);
    }

    // Epilogue: per-thread SwiGLU on (even n'=a, odd n'=g) -> smem fp16 -> 16B
    __syncthreads();
    __half* sh = (__half*)(smem + SM_TILES);    // [128][72]
    #pragma unroll
    for (int mf = 0; mf < 2; mf++) {
        #pragma unroll
        for (int nf = 0; nf < 8; nf++) {
            const float* c = acc[mf][nf];
            int jloc = (nbase >> 1) + nf * 4 + (lane & 3);
            #pragma unroll
            for (int r2 = 0; r2 < 2; r2++) {
                int mrow = mbase + mf*16 + (lane >> 2) + r2*8;
                float a = c[r2*2 + 0], g = c[r2*2 + 1];
                sh[mrow * 72 + jloc] = __float2half_rn(a * g / (1.f + __expf(-g)));
            }
        }
    }
    __syncthreads();
    const int j0 = blockIdx.y * 64;
    #pragma unroll
    for (int i = 0; i < 4; i++) {
        int idx = tid + i * 256;
        int r = idx >> 3, cb = idx & 7;
        if (m0 + r < cnt) {
            *(uint4*)(g_u + (size_t)rows_s[r] * HID + j0 + cb * 8) =
                *(const uint4*)(sh + r * 72 + cb * 8);
        }
    }
}

// ====================================================================
// Kernel 4: down GEMM (fp16) + skip add + scatter fp32
// ====================================================================
__global__ __launch_bounds__(256, 3)
void down_mma_kernel(const float* __restrict__ x, float* __restrict__ out) {
    extern __shared__ char smem[];
    int* rows_s = (int*)smem;
    const uint32_t sb = smem_u32(smem);
    const int tid = threadIdx.x, lane = tid & 31, wid = tid >> 5;
    const int e = blockIdx.z;
    const int cnt = g_count[e];
    const int m0 = blockIdx.x * 128;
    if (m0 >= cnt) return;
    const int n0 = blockIdx.y * 128;

    if (tid < 128) {
        int i = m0 + tid;
        rows_s[tid] = g_tokmap[e * NTOK + (i < cnt ? i : cnt - 1)];
    }
    __syncthreads();

    const __half* B = g_dw + (size_t)e * 1024 * 2048;

    const int NC = 32;   // 2048 / 64
    load_chunk(sb + SM_TILES, rows_s, tid, g_u, B, n0, 0, HID); CP_COMMIT();

    float acc[2][8][4];
    #pragma unroll
    for (int a = 0; a < 2; a++)
        #pragma unroll
        for (int b = 0; b < 8; b++)
            #pragma unroll
            for (int c = 0; c < 4; c++) acc[a][b][c] = 0.f;

    const int mbase = (wid & 3) * 32, nbase = (wid >> 2) * 64;

    #pragma unroll 1
    for (int c = 0; c < NC; c++) {
        asm volatile("cp.async.wait_group 0;" ::: "memory");
        __syncthreads();
        if (c + 1 < NC) {
            load_chunk(sb + SM_TILES + ((c+1)&1)*STAGE_SZ, rows_s, tid,
                       g_u, B, n0, (c+1)*64, HID);
            CP_COMMIT();
        }
        compute_chunk(sb + SM_TILES + (c&1)*STAGE_SZ, lane, mbase, nbase, acc);
    }

    // Epilogue: stage fp32 in smem, then coalesced skip-add + store
    __syncthreads();
    float* buf = (float*)(smem + SM_TILES);   // [128][132]
    #pragma unroll
    for (int mf = 0; mf < 2; mf++) {
        #pragma unroll
        for (int nf = 0; nf < 8; nf++) {
            const float* c = acc[mf][nf];
            int nloc = nbase + nf*8 + (lane & 3)*2;
            #pragma unroll
            for (int r2 = 0; r2 < 2; r2++) {
                int mrow = mbase + mf*16 + (lane >> 2) + r2*8;
                buf[mrow * 132 + nloc]     = c[r2*2 + 0];
                buf[mrow * 132 + nloc + 1] = c[r2*2 + 1];
            }
        }
    }
    __syncthreads();
    #pragma unroll
    for (int i = 0; i < 16; i++) {
        int idx = tid + i * 256;
        int r = idx >> 5, cb = idx & 31;
        if (m0 + r < cnt) {
            int token = rows_s[r];
            float4 v = *(const float4*)(buf + r * 132 + cb * 4);
            float4 s = *(const float4*)(x + (size_t)token * DIM + n0 + cb * 4);
            v.x += s.x; v.y += s.y; v.z += s.z; v.w += s.w;
            *(float4*)(out + (size_t)token * DIM + n0 + cb * 4) = v;
        }
    }
}

// ====================================================================
extern "C" void kernel_launch(void* const* d_in, const int* in_sizes, int n_in,
                              void* d_out, int out_size) {
    const float* x      = (const float*)d_in[0];   // [4,2048,1024]
    const float* scale  = (const float*)d_in[1];   // [1024]
    const float* cent   = (const float*)d_in[2];   // [8,1024]
    const float* up_w   = (const float*)d_in[3];   // [8,1024,4096]
    const float* down_w = (const float*)d_in[4];   // [8,2048,1024]
    float* out = (float*)d_out;                    // [4,2048,1024]

    cudaFuncSetAttribute(up_mma_kernel,   cudaFuncAttributeMaxDynamicSharedMemorySize, SMEM_MMA);
    cudaFuncSetAttribute(down_mma_kernel, cudaFuncAttributeMaxDynamicSharedMemorySize, SMEM_MMA);

    zero_counts_kernel<<<1, 32>>>();
    route_kernel<<<NTOK, 256>>>(x, scale, cent);
    conv_up_kernel<<<dim3(128, 16, NEXP), 256>>>(up_w);
    conv_down_kernel<<<dim3(32, 32, NEXP), 256>>>(down_w);
    up_mma_kernel<<<dim3(64, 32, NEXP), 256, SMEM_MMA>>>();
    down_mma_kernel<<<dim3(64, 8, NEXP), 256, SMEM_MMA>>>(x, out);
}

// round 13
// speedup vs baseline: 1.6947x; 1.6947x over previous
#include <cuda_runtime.h>
#include <cuda_fp16.h>
#include <math.h>
#include <stdint.h>

#define NTOK    8192
#define DIM     1024
#define HID     2048
#define NEXP    8

// ---------------- scratch (device globals; no allocation allowed) ----------
__device__ __half g_x16[(size_t)NTOK * DIM];          // x_norm fp16
__device__ __half g_uw[(size_t)NEXP * 4096 * 1024];   // up W^T fp16, n' interleaved (a,g)
__device__ __half g_dw[(size_t)NEXP * 1024 * 2048];   // down W^T fp16 [e][n][k]
__device__ __half g_u [(size_t)NTOK * HID];           // swiglu out fp16
__device__ int g_tokmap[NEXP * NTOK];
__device__ int g_count[NEXP];

// ---------------- helpers ----------------------------------------------
__device__ __forceinline__ uint32_t smem_u32(const void* p) {
    uint32_t a;
    asm("{ .reg .u64 t; cvta.to.shared.u64 t, %1; cvt.u32.u64 %0, t; }" : "=r"(a) : "l"(p));
    return a;
}
__device__ __forceinline__ void cp16(uint32_t dst, const void* src) {
    asm volatile("cp.async.cg.shared.global [%0], [%1], 16;" :: "r"(dst), "l"(src));
}
#define CP_COMMIT() asm volatile("cp.async.commit_group;")
#define SWZ128(o) ((o) ^ (((o) >> 3) & 0x70))

__device__ __forceinline__ uint32_t pack_h(float a, float b) {
    __half2 h = __floats2half2_rn(a, b);
    return *(uint32_t*)&h;
}
__device__ __forceinline__ void ldsm4(uint32_t* r, uint32_t addr) {
    asm volatile("ldmatrix.sync.aligned.m8n8.x4.shared.b16 {%0,%1,%2,%3}, [%4];"
        : "=r"(r[0]), "=r"(r[1]), "=r"(r[2]), "=r"(r[3]) : "r"(addr));
}
__device__ __forceinline__ void mma16816(float* c, const uint32_t* a, uint32_t b0, uint32_t b1) {
    asm volatile("mma.sync.aligned.m16n8k16.row.col.f32.f16.f16.f32 "
        "{%0,%1,%2,%3}, {%4,%5,%6,%7}, {%8,%9}, {%0,%1,%2,%3};"
        : "+f"(c[0]), "+f"(c[1]), "+f"(c[2]), "+f"(c[3])
        : "r"(a[0]), "r"(a[1]), "r"(a[2]), "r"(a[3]), "r"(b0), "r"(b1));
}

// ---------------- smem layout (BM=128, BN=64, BK=64 fp16, 3-stage) ---------
#define OFF_A    0          // 128 rows x 128B = 16384
#define OFF_B    16384      // 64 rows x 128B  = 8192
#define STAGE_SZ 24576
#define SM_TILES 1024
#define SMEM_MMA (1024 + 3*STAGE_SZ)   // 74752 B -> 3 CTAs/SM

// ====================================================================
__global__ void zero_counts_kernel() {
    if (threadIdx.x < NEXP) g_count[threadIdx.x] = 0;
}

// ====================================================================
// Kernel 1: RMSNorm + routing; writes x_norm fp16
// ====================================================================
__global__ __launch_bounds__(256)
void route_kernel(const float* __restrict__ x,
                  const float* __restrict__ scale,
                  const float* __restrict__ cent) {
    const int t = blockIdx.x, tid = threadIdx.x;
    const int lane = tid & 31, wid = tid >> 5;

    const float4 xv = ((const float4*)(x + (size_t)t * DIM))[tid];
    float ss = xv.x*xv.x + xv.y*xv.y + xv.z*xv.z + xv.w*xv.w;
    #pragma unroll
    for (int o = 16; o; o >>= 1) ss += __shfl_xor_sync(0xFFFFFFFFu, ss, o);
    __shared__ float swarp[8];
    if (lane == 0) swarp[wid] = ss;
    __syncthreads();
    float mean = 0.f;
    #pragma unroll
    for (int w = 0; w < 8; w++) mean += swarp[w];
    const float inv = rsqrtf(mean * (1.0f / DIM) + 1e-6f);

    const float4 sc = ((const float4*)scale)[tid];
    float v[4];
    v[0] = xv.x * (sc.x * inv); v[1] = xv.y * (sc.y * inv);
    v[2] = xv.z * (sc.z * inv); v[3] = xv.w * (sc.w * inv);

    ((uint2*)(g_x16 + (size_t)t * DIM))[tid] =
        make_uint2(pack_h(v[0], v[1]), pack_h(v[2], v[3]));

    float p[NEXP];
    #pragma unroll
    for (int e = 0; e < NEXP; e++) {
        const float4 c = ((const float4*)(cent + (size_t)e * DIM))[tid];
        p[e] = (c.x*c.x - 2.f*v[0]*c.x) + (c.y*c.y - 2.f*v[1]*c.y)
             + (c.z*c.z - 2.f*v[2]*c.z) + (c.w*c.w - 2.f*v[3]*c.w);
    }
    __shared__ float sred[NEXP][8];
    #pragma unroll
    for (int e = 0; e < NEXP; e++) {
        float s = p[e];
        #pragma unroll
        for (int o = 16; o; o >>= 1) s += __shfl_xor_sync(0xFFFFFFFFu, s, o);
        if (lane == 0) sred[e][wid] = s;
    }
    __syncthreads();
    if (tid == 0) {
        int best = 0; float bd = 3.4e38f;
        #pragma unroll
        for (int e = 0; e < NEXP; e++) {
            float d = 0.f;
            #pragma unroll
            for (int w = 0; w < 8; w++) d += sred[e][w];
            if (d < bd) { bd = d; best = e; }
        }
        int pos = atomicAdd(&g_count[best], 1);
        g_tokmap[best * NTOK + pos] = t;
    }
}

// ====================================================================
// Kernel 2a/2b: weight convert+transpose -> fp16, uint4 stores
// ====================================================================
__global__ __launch_bounds__(256)
void conv_up_kernel(const float* __restrict__ w) {   // [8][1024][4096]
    __shared__ float tile[32][65];
    const int e = blockIdx.z, n0 = blockIdx.x * 32, k0 = blockIdx.y * 64;
    const int tid = threadIdx.x;
    const float* W = w + ((size_t)e * 1024 + k0) * 4096 + n0;
    #pragma unroll
    for (int i = 0; i < 8; i++) {
        int idx = tid + i * 256;
        int kk = idx >> 5, nn = idx & 31;
        tile[nn][kk] = W[(size_t)kk * 4096 + nn];
    }
    __syncthreads();
    const int nn = tid >> 3, kq = tid & 7;
    const float* row = &tile[nn][kq * 8];
    uint4 v;
    v.x = pack_h(row[0], row[1]); v.y = pack_h(row[2], row[3]);
    v.z = pack_h(row[4], row[5]); v.w = pack_h(row[6], row[7]);
    int col = n0 + nn;
    int nprime = (col < 2048) ? (2 * col) : (2 * (col - 2048) + 1);
    *(uint4*)(g_uw + ((size_t)e * 4096 + nprime) * 1024 + k0 + kq * 8) = v;
}

__global__ __launch_bounds__(256)
void conv_down_kernel(const float* __restrict__ w) { // [8][2048][1024] -> [e][n][k]
    __shared__ float tile[32][65];
    const int e = blockIdx.z, n0 = blockIdx.x * 32, k0 = blockIdx.y * 64;
    const int tid = threadIdx.x;
    const float* W = w + ((size_t)e * 2048 + k0) * 1024 + n0;
    #pragma unroll
    for (int i = 0; i < 8; i++) {
        int idx = tid + i * 256;
        int kk = idx >> 5, nn = idx & 31;
        tile[nn][kk] = W[(size_t)kk * 1024 + nn];
    }
    __syncthreads();
    const int nn = tid >> 3, kq = tid & 7;
    const float* row = &tile[nn][kq * 8];
    uint4 v;
    v.x = pack_h(row[0], row[1]); v.y = pack_h(row[2], row[3]);
    v.z = pack_h(row[4], row[5]); v.w = pack_h(row[6], row[7]);
    *(uint4*)(g_dw + ((size_t)e * 1024 + n0 + nn) * 2048 + k0 + kq * 8) = v;
}

// ====================================================================
// Mainloop: BM=128, BN=64, BK=64 fp16, 256 thr, 8 warps (4m x 2n),
// warp tile 32m x 32n (acc=32 regs -> 3 CTAs/SM legal).
// ====================================================================
__device__ __forceinline__ void load_chunk(uint32_t st, const int* rows_s, int tid,
                                           const __half* A, const __half* B,
                                           int n0, int k0, int kstride) {
    #pragma unroll
    for (int i = 0; i < 4; i++) {                 // A: 1024 16B segs
        int idx = tid + i * 256;
        int r = idx >> 3, sg = idx & 7;
        uint32_t off = SWZ128((uint32_t)(r * 128 + sg * 16));
        cp16(st + OFF_A + off, A + (size_t)rows_s[r] * kstride + k0 + sg * 8);
    }
    #pragma unroll
    for (int i = 0; i < 2; i++) {                 // B: 512 16B segs
        int idx = tid + i * 256;
        int r = idx >> 3, sg = idx & 7;
        uint32_t off = SWZ128((uint32_t)(r * 128 + sg * 16));
        cp16(st + OFF_B + off, B + (size_t)(n0 + r) * kstride + k0 + sg * 8);
    }
}

__device__ __forceinline__ void compute_chunk(uint32_t st, int lane, int mbase, int nbase,
                                              float acc[2][4][4]) {
    const int rsel = lane & 15;
    const int csel = lane >> 4;
    #pragma unroll
    for (int k16 = 0; k16 < 4; k16++) {
        const int cg = k16 * 2 + csel;
        uint32_t a[2][4];
        #pragma unroll
        for (int mf = 0; mf < 2; mf++) {
            uint32_t boff = SWZ128((uint32_t)((mbase + mf*16 + rsel) * 128 + cg * 16));
            ldsm4(a[mf], st + OFF_A + boff);
        }
        #pragma unroll
        for (int q = 0; q < 2; q++) {
            uint32_t b[4];
            uint32_t boff = SWZ128((uint32_t)((nbase + q*16 + rsel) * 128 + cg * 16));
            ldsm4(b, st + OFF_B + boff);
            #pragma unroll
            for (int s = 0; s < 2; s++) {
                #pragma unroll
                for (int mf = 0; mf < 2; mf++)
                    mma16816(acc[mf][2*q + s], a[mf], b[s], b[2 + s]);
            }
        }
    }
}

// ====================================================================
// Kernel 3: up GEMM (fp16) + in-register SwiGLU (even n'=a, odd n'=g)
// CTA tile: 128 tokens x 64 n'  (-> 32 j-cols)
// ====================================================================
__global__ __launch_bounds__(256, 3)
void up_mma_kernel() {
    extern __shared__ char smem[];
    int* rows_s = (int*)smem;
    const uint32_t sb = smem_u32(smem);
    const int tid = threadIdx.x, lane = tid & 31, wid = tid >> 5;
    const int e = blockIdx.z;
    const int cnt = g_count[e];
    const int m0 = blockIdx.x * 128;
    if (m0 >= cnt) return;
    const int n0 = blockIdx.y * 64;      // n' base

    if (tid < 128) {
        int i = m0 + tid;
        rows_s[tid] = g_tokmap[e * NTOK + (i < cnt ? i : cnt - 1)];
    }
    __syncthreads();

    const __half* B = g_uw + (size_t)e * 4096 * 1024;

    const int NC = 16;   // 1024 / 64
    load_chunk(sb + SM_TILES,            rows_s, tid, g_x16, B, n0, 0,  DIM); CP_COMMIT();
    load_chunk(sb + SM_TILES + STAGE_SZ, rows_s, tid, g_x16, B, n0, 64, DIM); CP_COMMIT();

    float acc[2][4][4];
    #pragma unroll
    for (int a = 0; a < 2; a++)
        #pragma unroll
        for (int b = 0; b < 4; b++)
            #pragma unroll
            for (int c = 0; c < 4; c++) acc[a][b][c] = 0.f;

    const int mbase = (wid & 3) * 32, nbase = (wid >> 2) * 32;

    #pragma unroll 1
    for (int c = 0; c < NC; c++) {
        if (c < NC - 1) asm volatile("cp.async.wait_group 1;" ::: "memory");
        else            asm volatile("cp.async.wait_group 0;" ::: "memory");
        __syncthreads();
        if (c + 2 < NC) {
            load_chunk(sb + SM_TILES + ((c+2)%3)*STAGE_SZ, rows_s, tid,
                       g_x16, B, n0, (c+2)*64, DIM);
            CP_COMMIT();
        }
        compute_chunk(sb + SM_TILES + (c%3)*STAGE_SZ, lane, mbase, nbase, acc);
    }

    // Epilogue: per-thread SwiGLU on (even n'=a, odd n'=g) -> smem fp16 -> 16B
    __syncthreads();
    __half* sh = (__half*)(smem + SM_TILES);    // [128][40]
    #pragma unroll
    for (int mf = 0; mf < 2; mf++) {
        #pragma unroll
        for (int nf = 0; nf < 4; nf++) {
            const float* c = acc[mf][nf];
            int jloc = (nbase >> 1) + nf * 4 + (lane & 3);
            #pragma unroll
            for (int r2 = 0; r2 < 2; r2++) {
                int mrow = mbase + mf*16 + (lane >> 2) + r2*8;
                float a = c[r2*2 + 0], g = c[r2*2 + 1];
                sh[mrow * 40 + jloc] = __float2half_rn(a * g / (1.f + __expf(-g)));
            }
        }
    }
    __syncthreads();
    const int j0 = blockIdx.y * 32;
    #pragma unroll
    for (int i = 0; i < 2; i++) {
        int idx = tid + i * 256;
        int r = idx >> 2, cb = idx & 3;
        if (m0 + r < cnt) {
            *(uint4*)(g_u + (size_t)rows_s[r] * HID + j0 + cb * 8) =
                *(const uint4*)(sh + r * 40 + cb * 8);
        }
    }
}

// ====================================================================
// Kernel 4: down GEMM (fp16) + skip add + scatter fp32
// CTA tile: 128 tokens x 64 out-dims
// ====================================================================
__global__ __launch_bounds__(256, 3)
void down_mma_kernel(const float* __restrict__ x, float* __restrict__ out) {
    extern __shared__ char smem[];
    int* rows_s = (int*)smem;
    const uint32_t sb = smem_u32(smem);
    const int tid = threadIdx.x, lane = tid & 31, wid = tid >> 5;
    const int e = blockIdx.z;
    const int cnt = g_count[e];
    const int m0 = blockIdx.x * 128;
    if (m0 >= cnt) return;
    const int n0 = blockIdx.y * 64;

    if (tid < 128) {
        int i = m0 + tid;
        rows_s[tid] = g_tokmap[e * NTOK + (i < cnt ? i : cnt - 1)];
    }
    __syncthreads();

    const __half* B = g_dw + (size_t)e * 1024 * 2048;

    const int NC = 32;   // 2048 / 64
    load_chunk(sb + SM_TILES,            rows_s, tid, g_u, B, n0, 0,  HID); CP_COMMIT();
    load_chunk(sb + SM_TILES + STAGE_SZ, rows_s, tid, g_u, B, n0, 64, HID); CP_COMMIT();

    float acc[2][4][4];
    #pragma unroll
    for (int a = 0; a < 2; a++)
        #pragma unroll
        for (int b = 0; b < 4; b++)
            #pragma unroll
            for (int c = 0; c < 4; c++) acc[a][b][c] = 0.f;

    const int mbase = (wid & 3) * 32, nbase = (wid >> 2) * 32;

    #pragma unroll 1
    for (int c = 0; c < NC; c++) {
        if (c < NC - 1) asm volatile("cp.async.wait_group 1;" ::: "memory");
        else            asm volatile("cp.async.wait_group 0;" ::: "memory");
        __syncthreads();
        if (c + 2 < NC) {
            load_chunk(sb + SM_TILES + ((c+2)%3)*STAGE_SZ, rows_s, tid,
                       g_u, B, n0, (c+2)*64, HID);
            CP_COMMIT();
        }
        compute_chunk(sb + SM_TILES + (c%3)*STAGE_SZ, lane, mbase, nbase, acc);
    }

    // Epilogue: stage fp32 in smem, then coalesced skip-add + store
    __syncthreads();
    float* buf = (float*)(smem + SM_TILES);   // [128][68]
    #pragma unroll
    for (int mf = 0; mf < 2; mf++) {
        #pragma unroll
        for (int nf = 0; nf < 4; nf++) {
            const float* c = acc[mf][nf];
            int nloc = nbase + nf*8 + (lane & 3)*2;
            #pragma unroll
            for (int r2 = 0; r2 < 2; r2++) {
                int mrow = mbase + mf*16 + (lane >> 2) + r2*8;
                buf[mrow * 68 + nloc]     = c[r2*2 + 0];
                buf[mrow * 68 + nloc + 1] = c[r2*2 + 1];
            }
        }
    }
    __syncthreads();
    #pragma unroll
    for (int i = 0; i < 8; i++) {
        int idx = tid + i * 256;
        int r = idx >> 4, cb = idx & 15;
        if (m0 + r < cnt) {
            int token = rows_s[r];
            float4 v = *(const float4*)(buf + r * 68 + cb * 4);
            float4 s = *(const float4*)(x + (size_t)token * DIM + n0 + cb * 4);
            v.x += s.x; v.y += s.y; v.z += s.z; v.w += s.w;
            *(float4*)(out + (size_t)token * DIM + n0 + cb * 4) = v;
        }
    }
}

// ====================================================================
extern "C" void kernel_launch(void* const* d_in, const int* in_sizes, int n_in,
                              void* d_out, int out_size) {
    const float* x      = (const float*)d_in[0];   // [4,2048,1024]
    const float* scale  = (const float*)d_in[1];   // [1024]
    const float* cent   = (const float*)d_in[2];   // [8,1024]
    const float* up_w   = (const float*)d_in[3];   // [8,1024,4096]
    const float* down_w = (const float*)d_in[4];   // [8,2048,1024]
    float* out = (float*)d_out;                    // [4,2048,1024]

    cudaFuncSetAttribute(up_mma_kernel,   cudaFuncAttributeMaxDynamicSharedMemorySize, SMEM_MMA);
    cudaFuncSetAttribute(down_mma_kernel, cudaFuncAttributeMaxDynamicSharedMemorySize, SMEM_MMA);

    zero_counts_kernel<<<1, 32>>>();
    route_kernel<<<NTOK, 256>>>(x, scale, cent);
    conv_up_kernel<<<dim3(128, 16, NEXP), 256>>>(up_w);
    conv_down_kernel<<<dim3(32, 32, NEXP), 256>>>(down_w);
    up_mma_kernel<<<dim3(64, 64, NEXP), 256, SMEM_MMA>>>();
    down_mma_kernel<<<dim3(64, 16, NEXP), 256, SMEM_MMA>>>(x, out);
}

// round 14
// speedup vs baseline: 1.7672x; 1.0428x over previous
#include <cuda_runtime.h>
#include <cuda_fp16.h>
#include <math.h>
#include <stdint.h>

#define NTOK    8192
#define DIM     1024
#define HID     2048
#define NEXP    8
#define MAXT    72        // max total m-tiles: 64 + 8

// ---------------- scratch (device globals; no allocation allowed) ----------
__device__ __half g_x16[(size_t)NTOK * DIM];          // x_norm fp16
__device__ __half g_uw[(size_t)NEXP * 4096 * 1024];   // up W^T fp16, n' interleaved (a,g)
__device__ __half g_dw[(size_t)NEXP * 1024 * 2048];   // down W^T fp16 [e][n][k]
__device__ __half g_u [(size_t)NTOK * HID];           // swiglu out fp16
__device__ int g_tokmap[NEXP * NTOK];
__device__ int g_count[NEXP];
__device__ int g_tiles[MAXT];                         // (e<<16) | m_tile
__device__ int g_ntiles;

// ---------------- helpers ----------------------------------------------
__device__ __forceinline__ uint32_t smem_u32(const void* p) {
    uint32_t a;
    asm("{ .reg .u64 t; cvta.to.shared.u64 t, %1; cvt.u32.u64 %0, t; }" : "=r"(a) : "l"(p));
    return a;
}
__device__ __forceinline__ void cp16(uint32_t dst, const void* src) {
    asm volatile("cp.async.cg.shared.global [%0], [%1], 16;" :: "r"(dst), "l"(src));
}
__device__ __forceinline__ void cp16ca(uint32_t dst, const void* src) {
    asm volatile("cp.async.ca.shared.global [%0], [%1], 16;" :: "r"(dst), "l"(src));
}
#define CP_COMMIT() asm volatile("cp.async.commit_group;")
#define SWZ128(o) ((o) ^ (((o) >> 3) & 0x70))

__device__ __forceinline__ uint32_t pack_h(float a, float b) {
    __half2 h = __floats2half2_rn(a, b);
    return *(uint32_t*)&h;
}
__device__ __forceinline__ void ldsm4(uint32_t* r, uint32_t addr) {
    asm volatile("ldmatrix.sync.aligned.m8n8.x4.shared.b16 {%0,%1,%2,%3}, [%4];"
        : "=r"(r[0]), "=r"(r[1]), "=r"(r[2]), "=r"(r[3]) : "r"(addr));
}
__device__ __forceinline__ void mma16816(float* c, const uint32_t* a, uint32_t b0, uint32_t b1) {
    asm volatile("mma.sync.aligned.m16n8k16.row.col.f32.f16.f16.f32 "
        "{%0,%1,%2,%3}, {%4,%5,%6,%7}, {%8,%9}, {%0,%1,%2,%3};"
        : "+f"(c[0]), "+f"(c[1]), "+f"(c[2]), "+f"(c[3])
        : "r"(a[0]), "r"(a[1]), "r"(a[2]), "r"(a[3]), "r"(b0), "r"(b1));
}

// ---------------- smem layout (BM=128, BN=128, BK=64 fp16) -----------------
#define OFF_A    0
#define OFF_B    16384
#define STAGE_SZ 32768
#define SM_TILES 1024
#define SMEM_MMA (1024 + 3*STAGE_SZ)   // 99328 B -> 2 CTAs/SM

// ====================================================================
__global__ void zero_counts_kernel() {
    if (threadIdx.x < NEXP) g_count[threadIdx.x] = 0;
}

// ====================================================================
// Kernel 1: RMSNorm + routing; writes x_norm fp16
// ====================================================================
__global__ __launch_bounds__(256)
void route_kernel(const float* __restrict__ x,
                  const float* __restrict__ scale,
                  const float* __restrict__ cent) {
    const int t = blockIdx.x, tid = threadIdx.x;
    const int lane = tid & 31, wid = tid >> 5;

    const float4 xv = ((const float4*)(x + (size_t)t * DIM))[tid];
    float ss = xv.x*xv.x + xv.y*xv.y + xv.z*xv.z + xv.w*xv.w;
    #pragma unroll
    for (int o = 16; o; o >>= 1) ss += __shfl_xor_sync(0xFFFFFFFFu, ss, o);
    __shared__ float swarp[8];
    if (lane == 0) swarp[wid] = ss;
    __syncthreads();
    float mean = 0.f;
    #pragma unroll
    for (int w = 0; w < 8; w++) mean += swarp[w];
    const float inv = rsqrtf(mean * (1.0f / DIM) + 1e-6f);

    const float4 sc = ((const float4*)scale)[tid];
    float v[4];
    v[0] = xv.x * (sc.x * inv); v[1] = xv.y * (sc.y * inv);
    v[2] = xv.z * (sc.z * inv); v[3] = xv.w * (sc.w * inv);

    ((uint2*)(g_x16 + (size_t)t * DIM))[tid] =
        make_uint2(pack_h(v[0], v[1]), pack_h(v[2], v[3]));

    float p[NEXP];
    #pragma unroll
    for (int e = 0; e < NEXP; e++) {
        const float4 c = ((const float4*)(cent + (size_t)e * DIM))[tid];
        p[e] = (c.x*c.x - 2.f*v[0]*c.x) + (c.y*c.y - 2.f*v[1]*c.y)
             + (c.z*c.z - 2.f*v[2]*c.z) + (c.w*c.w - 2.f*v[3]*c.w);
    }
    __shared__ float sred[NEXP][8];
    #pragma unroll
    for (int e = 0; e < NEXP; e++) {
        float s = p[e];
        #pragma unroll
        for (int o = 16; o; o >>= 1) s += __shfl_xor_sync(0xFFFFFFFFu, s, o);
        if (lane == 0) sred[e][wid] = s;
    }
    __syncthreads();
    if (tid == 0) {
        int best = 0; float bd = 3.4e38f;
        #pragma unroll
        for (int e = 0; e < NEXP; e++) {
            float d = 0.f;
            #pragma unroll
            for (int w = 0; w < 8; w++) d += sred[e][w];
            if (d < bd) { bd = d; best = e; }
        }
        int pos = atomicAdd(&g_count[best], 1);
        g_tokmap[best * NTOK + pos] = t;
    }
}

// ====================================================================
// Kernel 1b: build flat (expert, m-tile) list
// ====================================================================
__global__ void prep_kernel() {
    if (threadIdx.x == 0) {
        int n = 0;
        #pragma unroll
        for (int e = 0; e < NEXP; e++) {
            int nt = (g_count[e] + 127) >> 7;
            for (int m = 0; m < nt; m++) g_tiles[n++] = (e << 16) | m;
        }
        g_ntiles = n;
    }
}

// ====================================================================
// Kernel 2a/2b: weight convert+transpose -> fp16, uint4 stores
// ====================================================================
__global__ __launch_bounds__(256)
void conv_up_kernel(const float* __restrict__ w) {   // [8][1024][4096]
    __shared__ float tile[32][65];
    const int e = blockIdx.z, n0 = blockIdx.x * 32, k0 = blockIdx.y * 64;
    const int tid = threadIdx.x;
    const float* W = w + ((size_t)e * 1024 + k0) * 4096 + n0;
    #pragma unroll
    for (int i = 0; i < 8; i++) {
        int idx = tid + i * 256;
        int kk = idx >> 5, nn = idx & 31;
        tile[nn][kk] = W[(size_t)kk * 4096 + nn];
    }
    __syncthreads();
    const int nn = tid >> 3, kq = tid & 7;
    const float* row = &tile[nn][kq * 8];
    uint4 v;
    v.x = pack_h(row[0], row[1]); v.y = pack_h(row[2], row[3]);
    v.z = pack_h(row[4], row[5]); v.w = pack_h(row[6], row[7]);
    int col = n0 + nn;
    int nprime = (col < 2048) ? (2 * col) : (2 * (col - 2048) + 1);
    *(uint4*)(g_uw + ((size_t)e * 4096 + nprime) * 1024 + k0 + kq * 8) = v;
}

__global__ __launch_bounds__(256)
void conv_down_kernel(const float* __restrict__ w) { // [8][2048][1024] -> [e][n][k]
    __shared__ float tile[32][65];
    const int e = blockIdx.z, n0 = blockIdx.x * 32, k0 = blockIdx.y * 64;
    const int tid = threadIdx.x;
    const float* W = w + ((size_t)e * 2048 + k0) * 1024 + n0;
    #pragma unroll
    for (int i = 0; i < 8; i++) {
        int idx = tid + i * 256;
        int kk = idx >> 5, nn = idx & 31;
        tile[nn][kk] = W[(size_t)kk * 1024 + nn];
    }
    __syncthreads();
    const int nn = tid >> 3, kq = tid & 7;
    const float* row = &tile[nn][kq * 8];
    uint4 v;
    v.x = pack_h(row[0], row[1]); v.y = pack_h(row[2], row[3]);
    v.z = pack_h(row[4], row[5]); v.w = pack_h(row[6], row[7]);
    *(uint4*)(g_dw + ((size_t)e * 1024 + n0 + nn) * 2048 + k0 + kq * 8) = v;
}

// ====================================================================
// Mainloop: BM=128, BN=128, BK=64 fp16, 256 thr, 8 warps (4m x 2n),
// warp tile 32m x 64n. A via .cg, B via .ca (L1 reuse by twin CTA).
// ====================================================================
__device__ __forceinline__ void load_chunk(uint32_t st, const int* rows_s, int tid,
                                           const __half* A, const __half* B,
                                           int n0, int k0, int kstride) {
    #pragma unroll
    for (int i = 0; i < 4; i++) {
        int idx = tid + i * 256;
        int r = idx >> 3, sg = idx & 7;
        uint32_t off = SWZ128((uint32_t)(r * 128 + sg * 16));
        cp16  (st + OFF_A + off, A + (size_t)rows_s[r] * kstride + k0 + sg * 8);
        cp16ca(st + OFF_B + off, B + (size_t)(n0 + r) * kstride + k0 + sg * 8);
    }
}

__device__ __forceinline__ void compute_chunk(uint32_t st, int lane, int mbase, int nbase,
                                              float acc[2][8][4]) {
    const int rsel = lane & 15;
    const int csel = lane >> 4;
    #pragma unroll
    for (int k16 = 0; k16 < 4; k16++) {
        const int cg = k16 * 2 + csel;
        uint32_t a[2][4];
        #pragma unroll
        for (int mf = 0; mf < 2; mf++) {
            uint32_t boff = SWZ128((uint32_t)((mbase + mf*16 + rsel) * 128 + cg * 16));
            ldsm4(a[mf], st + OFF_A + boff);
        }
        #pragma unroll
        for (int q = 0; q < 4; q++) {
            uint32_t b[4];
            uint32_t boff = SWZ128((uint32_t)((nbase + q*16 + rsel) * 128 + cg * 16));
            ldsm4(b, st + OFF_B + boff);
            #pragma unroll
            for (int s = 0; s < 2; s++) {
                #pragma unroll
                for (int mf = 0; mf < 2; mf++)
                    mma16816(acc[mf][2*q + s], a[mf], b[s], b[2 + s]);
            }
        }
    }
}

// ====================================================================
// Kernel 3: up GEMM (fp16) + in-register SwiGLU (even n'=a, odd n'=g)
// grid = (MAXT, 32); tile list lookup
// ====================================================================
__global__ __launch_bounds__(256, 2)
void up_mma_kernel() {
    extern __shared__ char smem[];
    int* rows_s = (int*)smem;
    const uint32_t sb = smem_u32(smem);
    const int tid = threadIdx.x, lane = tid & 31, wid = tid >> 5;

    if (blockIdx.x >= g_ntiles) return;
    const int te = g_tiles[blockIdx.x];
    const int e = te >> 16;
    const int cnt = g_count[e];
    const int m0 = (te & 0xFFFF) * 128;
    const int n0 = blockIdx.y * 128;     // n' base

    if (tid < 128) {
        int i = m0 + tid;
        rows_s[tid] = g_tokmap[e * NTOK + (i < cnt ? i : cnt - 1)];
    }
    __syncthreads();

    const __half* B = g_uw + (size_t)e * 4096 * 1024;

    const int NC = 16;   // 1024 / 64
    load_chunk(sb + SM_TILES,            rows_s, tid, g_x16, B, n0, 0,  DIM); CP_COMMIT();
    load_chunk(sb + SM_TILES + STAGE_SZ, rows_s, tid, g_x16, B, n0, 64, DIM); CP_COMMIT();

    float acc[2][8][4];
    #pragma unroll
    for (int a = 0; a < 2; a++)
        #pragma unroll
        for (int b = 0; b < 8; b++)
            #pragma unroll
            for (int c = 0; c < 4; c++) acc[a][b][c] = 0.f;

    const int mbase = (wid & 3) * 32, nbase = (wid >> 2) * 64;

    #pragma unroll 1
    for (int c = 0; c < NC; c++) {
        if (c < NC - 1) asm volatile("cp.async.wait_group 1;" ::: "memory");
        else            asm volatile("cp.async.wait_group 0;" ::: "memory");
        __syncthreads();
        if (c + 2 < NC) {
            load_chunk(sb + SM_TILES + ((c+2)%3)*STAGE_SZ, rows_s, tid,
                       g_x16, B, n0, (c+2)*64, DIM);
            CP_COMMIT();
        }
        compute_chunk(sb + SM_TILES + (c%3)*STAGE_SZ, lane, mbase, nbase, acc);
    }

    // Epilogue: per-thread SwiGLU on (even n'=a, odd n'=g) -> smem fp16 -> 16B
    __syncthreads();
    __half* sh = (__half*)(smem + SM_TILES);    // [128][72]
    #pragma unroll
    for (int mf = 0; mf < 2; mf++) {
        #pragma unroll
        for (int nf = 0; nf < 8; nf++) {
            const float* c = acc[mf][nf];
            int jloc = (nbase >> 1) + nf * 4 + (lane & 3);
            #pragma unroll
            for (int r2 = 0; r2 < 2; r2++) {
                int mrow = mbase + mf*16 + (lane >> 2) + r2*8;
                float a = c[r2*2 + 0], g = c[r2*2 + 1];
                sh[mrow * 72 + jloc] = __float2half_rn(a * g / (1.f + __expf(-g)));
            }
        }
    }
    __syncthreads();
    const int j0 = blockIdx.y * 64;
    #pragma unroll
    for (int i = 0; i < 4; i++) {
        int idx = tid + i * 256;
        int r = idx >> 3, cb = idx & 7;
        if (m0 + r < cnt) {
            *(uint4*)(g_u + (size_t)rows_s[r] * HID + j0 + cb * 8) =
                *(const uint4*)(sh + r * 72 + cb * 8);
        }
    }
}

// ====================================================================
// Kernel 4: down GEMM (fp16) + skip add + scatter fp32
// grid = (MAXT, 8); tile list lookup
// ====================================================================
__global__ __launch_bounds__(256, 2)
void down_mma_kernel(const float* __restrict__ x, float* __restrict__ out) {
    extern __shared__ char smem[];
    int* rows_s = (int*)smem;
    const uint32_t sb = smem_u32(smem);
    const int tid = threadIdx.x, lane = tid & 31, wid = tid >> 5;

    if (blockIdx.x >= g_ntiles) return;
    const int te = g_tiles[blockIdx.x];
    const int e = te >> 16;
    const int cnt = g_count[e];
    const int m0 = (te & 0xFFFF) * 128;
    const int n0 = blockIdx.y * 128;

    if (tid < 128) {
        int i = m0 + tid;
        rows_s[tid] = g_tokmap[e * NTOK + (i < cnt ? i : cnt - 1)];
    }
    __syncthreads();

    const __half* B = g_dw + (size_t)e * 1024 * 2048;

    const int NC = 32;   // 2048 / 64
    load_chunk(sb + SM_TILES,            rows_s, tid, g_u, B, n0, 0,  HID); CP_COMMIT();
    load_chunk(sb + SM_TILES + STAGE_SZ, rows_s, tid, g_u, B, n0, 64, HID); CP_COMMIT();

    float acc[2][8][4];
    #pragma unroll
    for (int a = 0; a < 2; a++)
        #pragma unroll
        for (int b = 0; b < 8; b++)
            #pragma unroll
            for (int c = 0; c < 4; c++) acc[a][b][c] = 0.f;

    const int mbase = (wid & 3) * 32, nbase = (wid >> 2) * 64;

    #pragma unroll 1
    for (int c = 0; c < NC; c++) {
        if (c < NC - 1) asm volatile("cp.async.wait_group 1;" ::: "memory");
        else            asm volatile("cp.async.wait_group 0;" ::: "memory");
        __syncthreads();
        if (c + 2 < NC) {
            load_chunk(sb + SM_TILES + ((c+2)%3)*STAGE_SZ, rows_s, tid,
                       g_u, B, n0, (c+2)*64, HID);
            CP_COMMIT();
        }
        compute_chunk(sb + SM_TILES + (c%3)*STAGE_SZ, lane, mbase, nbase, acc);
    }

    // Epilogue: stage fp32 in smem, then coalesced skip-add + store
    __syncthreads();
    float* buf = (float*)(smem + SM_TILES);   // [128][132]
    #pragma unroll
    for (int mf = 0; mf < 2; mf++) {
        #pragma unroll
        for (int nf = 0; nf < 8; nf++) {
            const float* c = acc[mf][nf];
            int nloc = nbase + nf*8 + (lane & 3)*2;
            #pragma unroll
            for (int r2 = 0; r2 < 2; r2++) {
                int mrow = mbase + mf*16 + (lane >> 2) + r2*8;
                buf[mrow * 132 + nloc]     = c[r2*2 + 0];
                buf[mrow * 132 + nloc + 1] = c[r2*2 + 1];
            }
        }
    }
    __syncthreads();
    #pragma unroll
    for (int i = 0; i < 16; i++) {
        int idx = tid + i * 256;
        int r = idx >> 5, cb = idx & 31;
        if (m0 + r < cnt) {
            int token = rows_s[r];
            float4 v = *(const float4*)(buf + r * 132 + cb * 4);
            float4 s = *(const float4*)(x + (size_t)token * DIM + n0 + cb * 4);
            v.x += s.x; v.y += s.y; v.z += s.z; v.w += s.w;
            *(float4*)(out + (size_t)token * DIM + n0 + cb * 4) = v;
        }
    }
}

// ====================================================================
extern "C" void kernel_launch(void* const* d_in, const int* in_sizes, int n_in,
                              void* d_out, int out_size) {
    const float* x      = (const float*)d_in[0];   // [4,2048,1024]
    const float* scale  = (const float*)d_in[1];   // [1024]
    const float* cent   = (const float*)d_in[2];   // [8,1024]
    const float* up_w   = (const float*)d_in[3];   // [8,1024,4096]
    const float* down_w = (const float*)d_in[4];   // [8,2048,1024]
    float* out = (float*)d_out;                    // [4,2048,1024]

    cudaFuncSetAttribute(up_mma_kernel,   cudaFuncAttributeMaxDynamicSharedMemorySize, SMEM_MMA);
    cudaFuncSetAttribute(down_mma_kernel, cudaFuncAttributeMaxDynamicSharedMemorySize, SMEM_MMA);

    zero_counts_kernel<<<1, 32>>>();
    route_kernel<<<NTOK, 256>>>(x, scale, cent);
    prep_kernel<<<1, 32>>>();
    conv_up_kernel<<<dim3(128, 16, NEXP), 256>>>(up_w);
    conv_down_kernel<<<dim3(32, 32, NEXP), 256>>>(down_w);
    up_mma_kernel<<<dim3(MAXT, 32), 256, SMEM_MMA>>>();
    down_mma_kernel<<<dim3(MAXT, 8), 256, SMEM_MMA>>>(x, out);
}

// round 15
// speedup vs baseline: 1.8847x; 1.0665x over previous
#include <cuda_runtime.h>
#include <cuda_fp16.h>
#include <math.h>
#include <stdint.h>

#define NTOK    8192
#define DIM     1024
#define HID     2048
#define NEXP    8
#define MAXT    72        // max total m-tiles: 64 + 8

// ---------------- scratch (device globals; no allocation allowed) ----------
__device__ __half g_x16[(size_t)NTOK * DIM];          // x_norm fp16
__device__ __half g_uw[(size_t)NEXP * 4096 * 1024];   // up W^T fp16, n' interleaved (a,g)
__device__ __half g_dw[(size_t)NEXP * 1024 * 2048];   // down W^T fp16 [e][n][k]
__device__ __half g_u [(size_t)NTOK * HID];           // swiglu out fp16
__device__ int g_tokmap[NEXP * NTOK];
__device__ int g_count[NEXP];
__device__ int g_tiles[MAXT];                         // (e<<16) | m_tile
__device__ int g_ntiles;

// ---------------- helpers ----------------------------------------------
__device__ __forceinline__ uint32_t smem_u32(const void* p) {
    uint32_t a;
    asm("{ .reg .u64 t; cvta.to.shared.u64 t, %1; cvt.u32.u64 %0, t; }" : "=r"(a) : "l"(p));
    return a;
}
__device__ __forceinline__ void cp16(uint32_t dst, const void* src) {
    asm volatile("cp.async.cg.shared.global [%0], [%1], 16;" :: "r"(dst), "l"(src));
}
#define CP_COMMIT() asm volatile("cp.async.commit_group;")
#define SWZ128(o) ((o) ^ (((o) >> 3) & 0x70))

__device__ __forceinline__ uint32_t pack_h(float a, float b) {
    __half2 h = __floats2half2_rn(a, b);
    return *(uint32_t*)&h;
}
__device__ __forceinline__ void ldsm4(uint32_t* r, uint32_t addr) {
    asm volatile("ldmatrix.sync.aligned.m8n8.x4.shared.b16 {%0,%1,%2,%3}, [%4];"
        : "=r"(r[0]), "=r"(r[1]), "=r"(r[2]), "=r"(r[3]) : "r"(addr));
}
__device__ __forceinline__ void mma16816(float* c, const uint32_t* a, uint32_t b0, uint32_t b1) {
    asm volatile("mma.sync.aligned.m16n8k16.row.col.f32.f16.f16.f32 "
        "{%0,%1,%2,%3}, {%4,%5,%6,%7}, {%8,%9}, {%0,%1,%2,%3};"
        : "+f"(c[0]), "+f"(c[1]), "+f"(c[2]), "+f"(c[3])
        : "r"(a[0]), "r"(a[1]), "r"(a[2]), "r"(a[3]), "r"(b0), "r"(b1));
}

// ---------------- smem layout (BM=128, BN=128, BK=64 fp16) -----------------
#define OFF_A    0
#define OFF_B    16384
#define STAGE_SZ 32768
#define SM_TILES 1024
#define SMEM_MMA (1024 + 3*STAGE_SZ)   // 99328 B -> 2 CTAs/SM

// ====================================================================
__global__ void zero_counts_kernel() {
    if (threadIdx.x < NEXP) g_count[threadIdx.x] = 0;
}

// ====================================================================
// Kernel 1: RMSNorm + routing; writes x_norm fp16
// ====================================================================
__global__ __launch_bounds__(256)
void route_kernel(const float* __restrict__ x,
                  const float* __restrict__ scale,
                  const float* __restrict__ cent) {
    const int t = blockIdx.x, tid = threadIdx.x;
    const int lane = tid & 31, wid = tid >> 5;

    const float4 xv = ((const float4*)(x + (size_t)t * DIM))[tid];
    float ss = xv.x*xv.x + xv.y*xv.y + xv.z*xv.z + xv.w*xv.w;
    #pragma unroll
    for (int o = 16; o; o >>= 1) ss += __shfl_xor_sync(0xFFFFFFFFu, ss, o);
    __shared__ float swarp[8];
    if (lane == 0) swarp[wid] = ss;
    __syncthreads();
    float mean = 0.f;
    #pragma unroll
    for (int w = 0; w < 8; w++) mean += swarp[w];
    const float inv = rsqrtf(mean * (1.0f / DIM) + 1e-6f);

    const float4 sc = ((const float4*)scale)[tid];
    float v[4];
    v[0] = xv.x * (sc.x * inv); v[1] = xv.y * (sc.y * inv);
    v[2] = xv.z * (sc.z * inv); v[3] = xv.w * (sc.w * inv);

    ((uint2*)(g_x16 + (size_t)t * DIM))[tid] =
        make_uint2(pack_h(v[0], v[1]), pack_h(v[2], v[3]));

    float p[NEXP];
    #pragma unroll
    for (int e = 0; e < NEXP; e++) {
        const float4 c = ((const float4*)(cent + (size_t)e * DIM))[tid];
        p[e] = (c.x*c.x - 2.f*v[0]*c.x) + (c.y*c.y - 2.f*v[1]*c.y)
             + (c.z*c.z - 2.f*v[2]*c.z) + (c.w*c.w - 2.f*v[3]*c.w);
    }
    __shared__ float sred[NEXP][8];
    #pragma unroll
    for (int e = 0; e < NEXP; e++) {
        float s = p[e];
        #pragma unroll
        for (int o = 16; o; o >>= 1) s += __shfl_xor_sync(0xFFFFFFFFu, s, o);
        if (lane == 0) sred[e][wid] = s;
    }
    __syncthreads();
    if (tid == 0) {
        int best = 0; float bd = 3.4e38f;
        #pragma unroll
        for (int e = 0; e < NEXP; e++) {
            float d = 0.f;
            #pragma unroll
            for (int w = 0; w < 8; w++) d += sred[e][w];
            if (d < bd) { bd = d; best = e; }
        }
        int pos = atomicAdd(&g_count[best], 1);
        g_tokmap[best * NTOK + pos] = t;
    }
}

// ====================================================================
// Kernel 1b: build flat (expert, m-tile) list
// ====================================================================
__global__ void prep_kernel() {
    if (threadIdx.x == 0) {
        int n = 0;
        #pragma unroll
        for (int e = 0; e < NEXP; e++) {
            int nt = (g_count[e] + 127) >> 7;
            for (int m = 0; m < nt; m++) g_tiles[n++] = (e << 16) | m;
        }
        g_ntiles = n;
    }
}

// ====================================================================
// Kernel 2a/2b: weight convert+transpose -> fp16, uint4 stores
// ====================================================================
__global__ __launch_bounds__(256)
void conv_up_kernel(const float* __restrict__ w) {   // [8][1024][4096]
    __shared__ float tile[32][65];
    const int e = blockIdx.z, n0 = blockIdx.x * 32, k0 = blockIdx.y * 64;
    const int tid = threadIdx.x;
    const float* W = w + ((size_t)e * 1024 + k0) * 4096 + n0;
    #pragma unroll
    for (int i = 0; i < 8; i++) {
        int idx = tid + i * 256;
        int kk = idx >> 5, nn = idx & 31;
        tile[nn][kk] = W[(size_t)kk * 4096 + nn];
    }
    __syncthreads();
    const int nn = tid >> 3, kq = tid & 7;
    const float* row = &tile[nn][kq * 8];
    uint4 v;
    v.x = pack_h(row[0], row[1]); v.y = pack_h(row[2], row[3]);
    v.z = pack_h(row[4], row[5]); v.w = pack_h(row[6], row[7]);
    int col = n0 + nn;
    int nprime = (col < 2048) ? (2 * col) : (2 * (col - 2048) + 1);
    *(uint4*)(g_uw + ((size_t)e * 4096 + nprime) * 1024 + k0 + kq * 8) = v;
}

__global__ __launch_bounds__(256)
void conv_down_kernel(const float* __restrict__ w) { // [8][2048][1024] -> [e][n][k]
    __shared__ float tile[32][65];
    const int e = blockIdx.z, n0 = blockIdx.x * 32, k0 = blockIdx.y * 64;
    const int tid = threadIdx.x;
    const float* W = w + ((size_t)e * 2048 + k0) * 1024 + n0;
    #pragma unroll
    for (int i = 0; i < 8; i++) {
        int idx = tid + i * 256;
        int kk = idx >> 5, nn = idx & 31;
        tile[nn][kk] = W[(size_t)kk * 1024 + nn];
    }
    __syncthreads();
    const int nn = tid >> 3, kq = tid & 7;
    const float* row = &tile[nn][kq * 8];
    uint4 v;
    v.x = pack_h(row[0], row[1]); v.y = pack_h(row[2], row[3]);
    v.z = pack_h(row[4], row[5]); v.w = pack_h(row[6], row[7]);
    *(uint4*)(g_dw + ((size_t)e * 1024 + n0 + nn) * 2048 + k0 + kq * 8) = v;
}

// ====================================================================
// Mainloop: BM=128, BN=128, BK=64 fp16, 256 thr, 8 warps (4m x 2n),
// warp tile 32m x 64n. All loads .cg (R11-proven).
// ====================================================================
__device__ __forceinline__ void load_chunk(uint32_t st, const int* rows_s, int tid,
                                           const __half* A, const __half* B,
                                           int n0, int k0, int kstride) {
    #pragma unroll
    for (int i = 0; i < 4; i++) {
        int idx = tid + i * 256;
        int r = idx >> 3, sg = idx & 7;
        uint32_t off = SWZ128((uint32_t)(r * 128 + sg * 16));
        cp16(st + OFF_A + off, A + (size_t)rows_s[r] * kstride + k0 + sg * 8);
        cp16(st + OFF_B + off, B + (size_t)(n0 + r) * kstride + k0 + sg * 8);
    }
}

__device__ __forceinline__ void compute_chunk(uint32_t st, int lane, int mbase, int nbase,
                                              float acc[2][8][4]) {
    const int rsel = lane & 15;
    const int csel = lane >> 4;
    #pragma unroll
    for (int k16 = 0; k16 < 4; k16++) {
        const int cg = k16 * 2 + csel;
        uint32_t a[2][4];
        #pragma unroll
        for (int mf = 0; mf < 2; mf++) {
            uint32_t boff = SWZ128((uint32_t)((mbase + mf*16 + rsel) * 128 + cg * 16));
            ldsm4(a[mf], st + OFF_A + boff);
        }
        #pragma unroll
        for (int q = 0; q < 4; q++) {
            uint32_t b[4];
            uint32_t boff = SWZ128((uint32_t)((nbase + q*16 + rsel) * 128 + cg * 16));
            ldsm4(b, st + OFF_B + boff);
            #pragma unroll
            for (int s = 0; s < 2; s++) {
                #pragma unroll
                for (int mf = 0; mf < 2; mf++)
                    mma16816(acc[mf][2*q + s], a[mf], b[s], b[2 + s]);
            }
        }
    }
}

// ====================================================================
// Kernel 3: up GEMM (fp16) + in-register SwiGLU (even n'=a, odd n'=g)
// grid = (MAXT, 32); flat tile list (dead-CTA elimination)
// ====================================================================
__global__ __launch_bounds__(256, 2)
void up_mma_kernel() {
    extern __shared__ char smem[];
    int* rows_s = (int*)smem;
    const uint32_t sb = smem_u32(smem);
    const int tid = threadIdx.x, lane = tid & 31, wid = tid >> 5;

    if (blockIdx.x >= g_ntiles) return;
    const int te = g_tiles[blockIdx.x];
    const int e = te >> 16;
    const int cnt = g_count[e];
    const int m0 = (te & 0xFFFF) * 128;
    const int n0 = blockIdx.y * 128;     // n' base

    if (tid < 128) {
        int i = m0 + tid;
        rows_s[tid] = g_tokmap[e * NTOK + (i < cnt ? i : cnt - 1)];
    }
    __syncthreads();

    const __half* B = g_uw + (size_t)e * 4096 * 1024;

    const int NC = 16;   // 1024 / 64
    load_chunk(sb + SM_TILES,            rows_s, tid, g_x16, B, n0, 0,  DIM); CP_COMMIT();
    load_chunk(sb + SM_TILES + STAGE_SZ, rows_s, tid, g_x16, B, n0, 64, DIM); CP_COMMIT();

    float acc[2][8][4];
    #pragma unroll
    for (int a = 0; a < 2; a++)
        #pragma unroll
        for (int b = 0; b < 8; b++)
            #pragma unroll
            for (int c = 0; c < 4; c++) acc[a][b][c] = 0.f;

    const int mbase = (wid & 3) * 32, nbase = (wid >> 2) * 64;

    #pragma unroll 1
    for (int c = 0; c < NC; c++) {
        if (c < NC - 1) asm volatile("cp.async.wait_group 1;" ::: "memory");
        else            asm volatile("cp.async.wait_group 0;" ::: "memory");
        __syncthreads();
        if (c + 2 < NC) {
            load_chunk(sb + SM_TILES + ((c+2)%3)*STAGE_SZ, rows_s, tid,
                       g_x16, B, n0, (c+2)*64, DIM);
            CP_COMMIT();
        }
        compute_chunk(sb + SM_TILES + (c%3)*STAGE_SZ, lane, mbase, nbase, acc);
    }

    // Epilogue: per-thread SwiGLU on (even n'=a, odd n'=g) -> smem fp16 -> 16B
    __syncthreads();
    __half* sh = (__half*)(smem + SM_TILES);    // [128][72]
    #pragma unroll
    for (int mf = 0; mf < 2; mf++) {
        #pragma unroll
        for (int nf = 0; nf < 8; nf++) {
            const float* c = acc[mf][nf];
            int jloc = (nbase >> 1) + nf * 4 + (lane & 3);
            #pragma unroll
            for (int r2 = 0; r2 < 2; r2++) {
                int mrow = mbase + mf*16 + (lane >> 2) + r2*8;
                float a = c[r2*2 + 0], g = c[r2*2 + 1];
                sh[mrow * 72 + jloc] = __float2half_rn(a * g / (1.f + __expf(-g)));
            }
        }
    }
    __syncthreads();
    const int j0 = blockIdx.y * 64;
    #pragma unroll
    for (int i = 0; i < 4; i++) {
        int idx = tid + i * 256;
        int r = idx >> 3, cb = idx & 7;
        if (m0 + r < cnt) {
            *(uint4*)(g_u + (size_t)rows_s[r] * HID + j0 + cb * 8) =
                *(const uint4*)(sh + r * 72 + cb * 8);
        }
    }
}

// ====================================================================
// Kernel 4: down GEMM (fp16) + skip add + scatter fp32
// grid = (MAXT, 8); flat tile list
// ====================================================================
__global__ __launch_bounds__(256, 2)
void down_mma_kernel(const float* __restrict__ x, float* __restrict__ out) {
    extern __shared__ char smem[];
    int* rows_s = (int*)smem;
    const uint32_t sb = smem_u32(smem);
    const int tid = threadIdx.x, lane = tid & 31, wid = tid >> 5;

    if (blockIdx.x >= g_ntiles) return;
    const int te = g_tiles[blockIdx.x];
    const int e = te >> 16;
    const int cnt = g_count[e];
    const int m0 = (te & 0xFFFF) * 128;
    const int n0 = blockIdx.y * 128;

    if (tid < 128) {
        int i = m0 + tid;
        rows_s[tid] = g_tokmap[e * NTOK + (i < cnt ? i : cnt - 1)];
    }
    __syncthreads();

    const __half* B = g_dw + (size_t)e * 1024 * 2048;

    const int NC = 32;   // 2048 / 64
    load_chunk(sb + SM_TILES,            rows_s, tid, g_u, B, n0, 0,  HID); CP_COMMIT();
    load_chunk(sb + SM_TILES + STAGE_SZ, rows_s, tid, g_u, B, n0, 64, HID); CP_COMMIT();

    float acc[2][8][4];
    #pragma unroll
    for (int a = 0; a < 2; a++)
        #pragma unroll
        for (int b = 0; b < 8; b++)
            #pragma unroll
            for (int c = 0; c < 4; c++) acc[a][b][c] = 0.f;

    const int mbase = (wid & 3) * 32, nbase = (wid >> 2) * 64;

    #pragma unroll 1
    for (int c = 0; c < NC; c++) {
        if (c < NC - 1) asm volatile("cp.async.wait_group 1;" ::: "memory");
        else            asm volatile("cp.async.wait_group 0;" ::: "memory");
        __syncthreads();
        if (c + 2 < NC) {
            load_chunk(sb + SM_TILES + ((c+2)%3)*STAGE_SZ, rows_s, tid,
                       g_u, B, n0, (c+2)*64, HID);
            CP_COMMIT();
        }
        compute_chunk(sb + SM_TILES + (c%3)*STAGE_SZ, lane, mbase, nbase, acc);
    }

    // Epilogue: stage fp32 in smem, then coalesced skip-add + store
    __syncthreads();
    float* buf = (float*)(smem + SM_TILES);   // [128][132]
    #pragma unroll
    for (int mf = 0; mf < 2; mf++) {
        #pragma unroll
        for (int nf = 0; nf < 8; nf++) {
            const float* c = acc[mf][nf];
            int nloc = nbase + nf*8 + (lane & 3)*2;
            #pragma unroll
            for (int r2 = 0; r2 < 2; r2++) {
                int mrow = mbase + mf*16 + (lane >> 2) + r2*8;
                buf[mrow * 132 + nloc]     = c[r2*2 + 0];
                buf[mrow * 132 + nloc + 1] = c[r2*2 + 1];
            }
        }
    }
    __syncthreads();
    #pragma unroll
    for (int i = 0; i < 16; i++) {
        int idx = tid + i * 256;
        int r = idx >> 5, cb = idx & 31;
        if (m0 + r < cnt) {
            int token = rows_s[r];
            float4 v = *(const float4*)(buf + r * 132 + cb * 4);
            float4 s = *(const float4*)(x + (size_t)token * DIM + n0 + cb * 4);
            v.x += s.x; v.y += s.y; v.z += s.z; v.w += s.w;
            *(float4*)(out + (size_t)token * DIM + n0 + cb * 4) = v;
        }
    }
}

// ====================================================================
extern "C" void kernel_launch(void* const* d_in, const int* in_sizes, int n_in,
                              void* d_out, int out_size) {
    const float* x      = (const float*)d_in[0];   // [4,2048,1024]
    const float* scale  = (const float*)d_in[1];   // [1024]
    const float* cent   = (const float*)d_in[2];   // [8,1024]
    const float* up_w   = (const float*)d_in[3];   // [8,1024,4096]
    const float* down_w = (const float*)d_in[4];   // [8,2048,1024]
    float* out = (float*)d_out;                    // [4,2048,1024]

    cudaFuncSetAttribute(up_mma_kernel,   cudaFuncAttributeMaxDynamicSharedMemorySize, SMEM_MMA);
    cudaFuncSetAttribute(down_mma_kernel, cudaFuncAttributeMaxDynamicSharedMemorySize, SMEM_MMA);

    zero_counts_kernel<<<1, 32>>>();
    route_kernel<<<NTOK, 256>>>(x, scale, cent);
    prep_kernel<<<1, 32>>>();
    conv_up_kernel<<<dim3(128, 16, NEXP), 256>>>(up_w);
    conv_down_kernel<<<dim3(32, 32, NEXP), 256>>>(down_w);
    up_mma_kernel<<<dim3(MAXT, 32), 256, SMEM_MMA>>>();
    down_mma_kernel<<<dim3(MAXT, 8), 256, SMEM_MMA>>>(x, out);
}